// round 2
// baseline (speedup 1.0000x reference)
#include <cuda_runtime.h>
#include <math.h>

#define N_USERS 100000
#define N_ITEMS 200000
#define N_NODES 300000
#define EMB_DIM 64
#define N_EDGES 4000000
#define BATCH   8192
#define EMB_REG 2.5e-05f

// ---------------- scratch (device globals; no allocation allowed) ----------------
static __device__ float g_deg  [N_NODES];
static __device__ float g_dinv [N_NODES];
static __device__ float g_gvals[N_EDGES];
static __device__ float g_E  [(size_t)N_NODES * EMB_DIM];
static __device__ float g_N  [(size_t)N_NODES * EMB_DIM];
static __device__ float g_ACC[(size_t)N_NODES * EMB_DIM];

// ---------------- kernels ----------------

// zero degree array and the 2-float output
__global__ void k_zero(float* out) {
    int i = blockIdx.x * blockDim.x + threadIdx.x;
    if (i < N_NODES) g_deg[i] = 0.0f;
    if (i < 2)       out[i]   = 0.0f;
}

__global__ void k_deg(const int* __restrict__ h) {
    int e = blockIdx.x * blockDim.x + threadIdx.x;
    if (e < N_EDGES) atomicAdd(&g_deg[__ldg(h + e)], 1.0f);
}

__global__ void k_dinv() {
    int i = blockIdx.x * blockDim.x + threadIdx.x;
    if (i < N_NODES) {
        float d = g_deg[i];
        g_dinv[i] = (d > 0.0f) ? rsqrtf(d) : 0.0f;
    }
}

__global__ void k_gvals(const int* __restrict__ h, const int* __restrict__ t) {
    int e = blockIdx.x * blockDim.x + threadIdx.x;
    if (e < N_EDGES) g_gvals[e] = g_dinv[__ldg(h + e)] * g_dinv[__ldg(t + e)];
}

// E = concat(user_emb, item_emb); ACC = E   (float4 granularity)
__global__ void k_init(const float* __restrict__ ue, const float* __restrict__ ie) {
    int i = blockIdx.x * blockDim.x + threadIdx.x;   // float4 index
    const int TOT = N_NODES * (EMB_DIM / 4);
    if (i >= TOT) return;
    const int UQ = N_USERS * (EMB_DIM / 4);
    float4 v = (i < UQ) ? reinterpret_cast<const float4*>(ue)[i]
                        : reinterpret_cast<const float4*>(ie)[i - UQ];
    reinterpret_cast<float4*>(g_E)[i]   = v;
    reinterpret_cast<float4*>(g_ACC)[i] = v;
}

// dst = src  (so that subsequent spmm-atomics produce A*src + src)
__global__ void k_copy(int layer) {
    int i = blockIdx.x * blockDim.x + threadIdx.x;
    const int TOT = N_NODES * (EMB_DIM / 4);
    if (i >= TOT) return;
    if (layer == 0)
        reinterpret_cast<float4*>(g_N)[i] = reinterpret_cast<const float4*>(g_E)[i];
    else
        reinterpret_cast<float4*>(g_E)[i] = reinterpret_cast<const float4*>(g_N)[i];
}

// scatter: dst[h] += g * src[t]  ; 16 threads per edge, 4 dims each (float4 load)
__global__ void k_spmm(const int* __restrict__ h, const int* __restrict__ t, int layer) {
    const float* __restrict__ src = (layer == 0) ? g_E : g_N;
    float*       __restrict__ dst = (layer == 0) ? g_N : g_E;
    long long gid = (long long)blockIdx.x * blockDim.x + threadIdx.x;
    int e    = (int)(gid >> 4);
    int part = (int)(gid & 15);
    if (e >= N_EDGES) return;
    float g  = g_gvals[e];
    int   tt = __ldg(t + e);
    int   hh = __ldg(h + e);
    float4 v = reinterpret_cast<const float4*>(src + (size_t)tt * EMB_DIM)[part];
    float* dp = dst + (size_t)hh * EMB_DIM + part * 4;
    atomicAdd(dp + 0, g * v.x);
    atomicAdd(dp + 1, g * v.y);
    atomicAdd(dp + 2, g * v.z);
    atomicAdd(dp + 3, g * v.w);
}

// ACC += (layer==0 ? N : E)
__global__ void k_acc(int layer) {
    int i = blockIdx.x * blockDim.x + threadIdx.x;
    const int TOT = N_NODES * (EMB_DIM / 4);
    if (i >= TOT) return;
    float4 v = (layer == 0) ? reinterpret_cast<const float4*>(g_N)[i]
                            : reinterpret_cast<const float4*>(g_E)[i];
    float4 a = reinterpret_cast<float4*>(g_ACC)[i];
    a.x += v.x; a.y += v.y; a.z += v.z; a.w += v.w;
    reinterpret_cast<float4*>(g_ACC)[i] = a;
}

// one warp per sample: scores from ACC, reg from pre-embeddings
__global__ void k_loss(const float* __restrict__ ue, const float* __restrict__ ie,
                       const int* __restrict__ users, const int* __restrict__ pos,
                       const int* __restrict__ neg, float* __restrict__ out) {
    int warp = (blockIdx.x * blockDim.x + threadIdx.x) >> 5;
    int lane = threadIdx.x & 31;
    if (warp >= BATCH) return;
    int u = users[warp], p = pos[warp], n = neg[warp];

    const float2* ua = reinterpret_cast<const float2*>(g_ACC + (size_t)u * EMB_DIM);
    const float2* pa = reinterpret_cast<const float2*>(g_ACC + (size_t)(N_USERS + p) * EMB_DIM);
    const float2* na = reinterpret_cast<const float2*>(g_ACC + (size_t)(N_USERS + n) * EMB_DIM);
    float2 uv = ua[lane], pv = pa[lane], nv = na[lane];
    float s = uv.x * (nv.x - pv.x) + uv.y * (nv.y - pv.y);   // neg_score - pos_score (partial)

    const float2* up = reinterpret_cast<const float2*>(ue + (size_t)u * EMB_DIM);
    const float2* pp = reinterpret_cast<const float2*>(ie + (size_t)p * EMB_DIM);
    const float2* np = reinterpret_cast<const float2*>(ie + (size_t)n * EMB_DIM);
    float2 a = up[lane], b = pp[lane], c = np[lane];
    float r = a.x*a.x + a.y*a.y + b.x*b.x + b.y*b.y + c.x*c.x + c.y*c.y;

    #pragma unroll
    for (int o = 16; o; o >>= 1) {
        s += __shfl_xor_sync(0xFFFFFFFFu, s, o);
        r += __shfl_xor_sync(0xFFFFFFFFu, r, o);
    }
    if (lane == 0) {
        float x  = s;
        float sp = (x > 0.0f) ? x + log1pf(expf(-x)) : log1pf(expf(x));
        atomicAdd(&out[0], sp * (1.0f / BATCH));
        atomicAdd(&out[1], r * EMB_REG);
    }
}

// ---------------- launch ----------------
extern "C" void kernel_launch(void* const* d_in, const int* in_sizes, int n_in,
                              void* d_out, int out_size) {
    const float* ue    = (const float*)d_in[0];
    const float* ie    = (const float*)d_in[1];
    const int*   all_h = (const int*)  d_in[2];
    const int*   all_t = (const int*)  d_in[3];
    const int*   users = (const int*)  d_in[4];
    const int*   pos   = (const int*)  d_in[5];
    const int*   neg   = (const int*)  d_in[6];
    float*       out   = (float*)d_out;

    const int T = 256;
    const int TOT4   = N_NODES * (EMB_DIM / 4);               // 4.8M float4 slots
    const int gNode  = (N_NODES + T - 1) / T;
    const int gEdge  = (N_EDGES + T - 1) / T;
    const int gVec   = (TOT4 + T - 1) / T;
    const long long spmmThreads = (long long)N_EDGES * 16;
    const int gSpmm  = (int)((spmmThreads + T - 1) / T);

    k_zero <<<gNode, T>>>(out);
    k_deg  <<<gEdge, T>>>(all_h);
    k_dinv <<<gNode, T>>>();
    k_gvals<<<gEdge, T>>>(all_h, all_t);
    k_init <<<gVec,  T>>>(ue, ie);

    for (int layer = 0; layer < 2; ++layer) {
        k_copy<<<gVec,  T>>>(layer);
        k_spmm<<<gSpmm, T>>>(all_h, all_t, layer);
        k_acc <<<gVec,  T>>>(layer);
    }

    k_loss<<<(BATCH * 32 + T - 1) / T, T>>>(ue, ie, users, pos, neg, out);
}

// round 3
// speedup vs baseline: 1.6707x; 1.6707x over previous
#include <cuda_runtime.h>
#include <math.h>

#define N_USERS 100000
#define N_ITEMS 200000
#define N_NODES 300000
#define EMB_DIM 64
#define VEC     16          // EMB_DIM/4 float4s per row
#define N_EDGES 4000000
#define BATCH   8192
#define EMB_REG 2.5e-05f

// ---------------- scratch (device globals; 16B-aligned via float4) ----------------
static __device__ float  g_deg  [N_NODES];
static __device__ float  g_dinv [N_NODES];
static __device__ float  g_gvals[N_EDGES];
static __device__ float4 g_E  [(size_t)N_NODES * VEC];
static __device__ float4 g_N  [(size_t)N_NODES * VEC];
static __device__ float4 g_ACC[(size_t)N_NODES * VEC];

// ---------------- kernels ----------------

__global__ void k_zero(float* out) {
    int i = blockIdx.x * blockDim.x + threadIdx.x;
    if (i < N_NODES) g_deg[i] = 0.0f;
    if (i < 2)       out[i]   = 0.0f;
}

__global__ void k_deg(const int* __restrict__ h) {
    int e = blockIdx.x * blockDim.x + threadIdx.x;
    if (e < N_EDGES) atomicAdd(&g_deg[__ldg(h + e)], 1.0f);
}

__global__ void k_dinv() {
    int i = blockIdx.x * blockDim.x + threadIdx.x;
    if (i < N_NODES) {
        float d = g_deg[i];
        g_dinv[i] = (d > 0.0f) ? rsqrtf(d) : 0.0f;
    }
}

__global__ void k_gvals(const int* __restrict__ h, const int* __restrict__ t) {
    int e = blockIdx.x * blockDim.x + threadIdx.x;
    if (e < N_EDGES) g_gvals[e] = g_dinv[__ldg(h + e)] * g_dinv[__ldg(t + e)];
}

// E = concat(user_emb, item_emb); ACC = E   (float4 granularity)
__global__ void k_init(const float* __restrict__ ue, const float* __restrict__ ie) {
    int i = blockIdx.x * blockDim.x + threadIdx.x;   // float4 index
    const int TOT = N_NODES * VEC;
    if (i >= TOT) return;
    const int UQ = N_USERS * VEC;
    float4 v = (i < UQ) ? __ldg(reinterpret_cast<const float4*>(ue) + i)
                        : __ldg(reinterpret_cast<const float4*>(ie) + (i - UQ));
    g_E[i]   = v;
    g_ACC[i] = v;
}

// dst = src  (residual pre-load so spmm-atomics produce A*src + src)
__global__ void k_copy(int layer) {
    int i = blockIdx.x * blockDim.x + threadIdx.x;
    const int TOT = N_NODES * VEC;
    if (i >= TOT) return;
    if (layer == 0) g_N[i] = g_E[i];
    else            g_E[i] = g_N[i];
}

// scatter: dst[h] += g * src[t] ; 16 threads per edge, one float4 + one red.v4 each
__global__ void k_spmm(const int* __restrict__ h, const int* __restrict__ t, int layer) {
    const float4* __restrict__ src = (layer == 0) ? g_E : g_N;
    float4*       __restrict__ dst = (layer == 0) ? g_N : g_E;
    long long gid = (long long)blockIdx.x * blockDim.x + threadIdx.x;
    int e    = (int)(gid >> 4);
    int part = (int)(gid & 15);
    if (e >= N_EDGES) return;
    float g  = g_gvals[e];
    int   tt = __ldg(t + e);
    int   hh = __ldg(h + e);
    float4 v = __ldg(&src[(size_t)tt * VEC + part]);
    float4* dp = &dst[(size_t)hh * VEC + part];
    asm volatile("red.global.v4.f32.add [%0], {%1, %2, %3, %4};"
                 :: "l"(dp), "f"(g * v.x), "f"(g * v.y), "f"(g * v.z), "f"(g * v.w)
                 : "memory");
}

// ACC += (layer==0 ? N : E)
__global__ void k_acc(int layer) {
    int i = blockIdx.x * blockDim.x + threadIdx.x;
    const int TOT = N_NODES * VEC;
    if (i >= TOT) return;
    float4 v = (layer == 0) ? g_N[i] : g_E[i];
    float4 a = g_ACC[i];
    a.x += v.x; a.y += v.y; a.z += v.z; a.w += v.w;
    g_ACC[i] = a;
}

// one warp per sample: scores from ACC, reg from pre-embeddings
__global__ void k_loss(const float* __restrict__ ue, const float* __restrict__ ie,
                       const int* __restrict__ users, const int* __restrict__ pos,
                       const int* __restrict__ neg, float* __restrict__ out) {
    int warp = (blockIdx.x * blockDim.x + threadIdx.x) >> 5;
    int lane = threadIdx.x & 31;
    if (warp >= BATCH) return;
    int u = users[warp], p = pos[warp], n = neg[warp];

    const float2* ua = reinterpret_cast<const float2*>(g_ACC + (size_t)u * VEC);
    const float2* pa = reinterpret_cast<const float2*>(g_ACC + (size_t)(N_USERS + p) * VEC);
    const float2* na = reinterpret_cast<const float2*>(g_ACC + (size_t)(N_USERS + n) * VEC);
    float2 uv = ua[lane], pv = pa[lane], nv = na[lane];
    float s = uv.x * (nv.x - pv.x) + uv.y * (nv.y - pv.y);   // neg - pos partial

    const float2* up = reinterpret_cast<const float2*>(ue + (size_t)u * EMB_DIM);
    const float2* pp = reinterpret_cast<const float2*>(ie + (size_t)p * EMB_DIM);
    const float2* np = reinterpret_cast<const float2*>(ie + (size_t)n * EMB_DIM);
    float2 a = up[lane], b = pp[lane], c = np[lane];
    float r = a.x*a.x + a.y*a.y + b.x*b.x + b.y*b.y + c.x*c.x + c.y*c.y;

    #pragma unroll
    for (int o = 16; o; o >>= 1) {
        s += __shfl_xor_sync(0xFFFFFFFFu, s, o);
        r += __shfl_xor_sync(0xFFFFFFFFu, r, o);
    }
    if (lane == 0) {
        float x  = s;
        float sp = (x > 0.0f) ? x + log1pf(expf(-x)) : log1pf(expf(x));
        atomicAdd(&out[0], sp * (1.0f / BATCH));
        atomicAdd(&out[1], r * EMB_REG);
    }
}

// ---------------- launch ----------------
extern "C" void kernel_launch(void* const* d_in, const int* in_sizes, int n_in,
                              void* d_out, int out_size) {
    const float* ue    = (const float*)d_in[0];
    const float* ie    = (const float*)d_in[1];
    const int*   all_h = (const int*)  d_in[2];
    const int*   all_t = (const int*)  d_in[3];
    const int*   users = (const int*)  d_in[4];
    const int*   pos   = (const int*)  d_in[5];
    const int*   neg   = (const int*)  d_in[6];
    float*       out   = (float*)d_out;

    const int T = 256;
    const int TOT4  = N_NODES * VEC;                          // 4.8M float4 slots
    const int gNode = (N_NODES + T - 1) / T;
    const int gEdge = (N_EDGES + T - 1) / T;
    const int gVec  = (TOT4 + T - 1) / T;
    const long long spmmThreads = (long long)N_EDGES * 16;
    const int gSpmm = (int)((spmmThreads + T - 1) / T);

    k_zero <<<gNode, T>>>(out);
    k_deg  <<<gEdge, T>>>(all_h);
    k_dinv <<<gNode, T>>>();
    k_gvals<<<gEdge, T>>>(all_h, all_t);
    k_init <<<gVec,  T>>>(ue, ie);

    for (int layer = 0; layer < 2; ++layer) {
        k_copy<<<gVec,  T>>>(layer);
        k_spmm<<<gSpmm, T>>>(all_h, all_t, layer);
        k_acc <<<gVec,  T>>>(layer);
    }

    k_loss<<<(BATCH * 32 + T - 1) / T, T>>>(ue, ie, users, pos, neg, out);
}

// round 4
// speedup vs baseline: 2.9612x; 1.7724x over previous
#include <cuda_runtime.h>
#include <math.h>

#define N_USERS 100000
#define N_ITEMS 200000
#define N_NODES 300000
#define EMB_DIM 64
#define VEC     16          // float4s per row
#define N_EDGES 4000000
#define BATCH   8192
#define EMB_REG 2.5e-05f
#define SCAN_BLK 256
#define NBLK ((N_NODES + SCAN_BLK - 1) / SCAN_BLK)   // 1172

// ---------------- scratch (device globals) ----------------
static __device__ int    g_cnt   [N_NODES];
static __device__ int    g_rowptr[N_NODES + 1];
static __device__ int    g_cursor[N_NODES];
static __device__ int    g_blksum[NBLK];
static __device__ float  g_dinv  [N_NODES];
static __device__ int    g_ts    [N_EDGES];      // CSR col indices (t), sorted by h
static __device__ float  g_gs    [N_EDGES];      // CSR edge weights
static __device__ float4 g_E  [(size_t)N_NODES * VEC];
static __device__ float4 g_N  [(size_t)N_NODES * VEC];
static __device__ float4 g_ACC[(size_t)N_NODES * VEC];

// ---------------- kernels ----------------

__global__ void k_zero(float* out) {
    int i = blockIdx.x * blockDim.x + threadIdx.x;
    if (i < N_NODES) g_cnt[i] = 0;
    if (i < 2)       out[i]   = 0.0f;
}

__global__ void k_deg(const int* __restrict__ h) {
    int e = blockIdx.x * blockDim.x + threadIdx.x;
    if (e < N_EDGES) atomicAdd(&g_cnt[__ldg(h + e)], 1);
}

// block-local exclusive scan; block totals to g_blksum
__global__ void k_scan1() {
    __shared__ int sh[SCAN_BLK];
    int i = blockIdx.x * SCAN_BLK + threadIdx.x;
    int v = (i < N_NODES) ? g_cnt[i] : 0;
    sh[threadIdx.x] = v;
    __syncthreads();
    for (int o = 1; o < SCAN_BLK; o <<= 1) {
        int t = (threadIdx.x >= o) ? sh[threadIdx.x - o] : 0;
        __syncthreads();
        sh[threadIdx.x] += t;
        __syncthreads();
    }
    if (i < N_NODES) g_rowptr[i] = sh[threadIdx.x] - v;          // exclusive
    if (threadIdx.x == SCAN_BLK - 1) g_blksum[blockIdx.x] = sh[SCAN_BLK - 1];
}

// single-block exclusive scan of the 1172 block sums
__global__ void k_scan2() {
    __shared__ int sh[1024];
    __shared__ int carry;
    int tid = threadIdx.x;
    if (tid == 0) carry = 0;
    __syncthreads();
    for (int base = 0; base < NBLK; base += 1024) {
        int i = base + tid;
        int v = (i < NBLK) ? g_blksum[i] : 0;
        sh[tid] = v;
        __syncthreads();
        for (int o = 1; o < 1024; o <<= 1) {
            int t = (tid >= o) ? sh[tid - o] : 0;
            __syncthreads();
            sh[tid] += t;
            __syncthreads();
        }
        if (i < NBLK) g_blksum[i] = sh[tid] - v + carry;
        __syncthreads();
        if (tid == 0) carry += sh[1023];
        __syncthreads();
    }
}

// finalize rowptr, init cursor, compute dinv
__global__ void k_scan3() {
    int i = blockIdx.x * blockDim.x + threadIdx.x;
    if (i < N_NODES) {
        int rp = g_rowptr[i] + g_blksum[i >> 8];
        g_rowptr[i] = rp;
        g_cursor[i] = rp;
        int c = g_cnt[i];
        g_dinv[i] = (c > 0) ? rsqrtf((float)c) : 0.0f;
    }
    if (i == 0) g_rowptr[N_NODES] = N_EDGES;
}

// counting-sort scatter: bucket edges by h; weight computed on the fly
__global__ void k_scatter(const int* __restrict__ h, const int* __restrict__ t) {
    int e = blockIdx.x * blockDim.x + threadIdx.x;
    if (e >= N_EDGES) return;
    int hh = __ldg(h + e);
    int tt = __ldg(t + e);
    int slot = atomicAdd(&g_cursor[hh], 1);
    g_ts[slot] = tt;
    g_gs[slot] = g_dinv[hh] * g_dinv[tt];
}

// E = concat(user_emb, item_emb); ACC = E
__global__ void k_init(const float* __restrict__ ue, const float* __restrict__ ie) {
    int i = blockIdx.x * blockDim.x + threadIdx.x;
    const int TOT = N_NODES * VEC;
    if (i >= TOT) return;
    const int UQ = N_USERS * VEC;
    float4 v = (i < UQ) ? __ldg(reinterpret_cast<const float4*>(ue) + i)
                        : __ldg(reinterpret_cast<const float4*>(ie) + (i - UQ));
    g_E[i]   = v;
    g_ACC[i] = v;
}

// warp-per-row CSR SpMM with fused residual + ACC update (+ next-layer src write)
__global__ void k_csr(int layer) {
    int wg   = (blockIdx.x * blockDim.x + threadIdx.x) >> 5;
    int lane = threadIdx.x & 31;
    if (wg >= N_NODES) return;
    const float2* __restrict__ src = reinterpret_cast<const float2*>(layer == 0 ? g_E : g_N);

    int beg = g_rowptr[wg];
    int end = g_rowptr[wg + 1];
    float2 acc = make_float2(0.0f, 0.0f);

    int e = beg;
    for (; e + 2 <= end; e += 2) {
        int   t0 = __ldg(g_ts + e),     t1 = __ldg(g_ts + e + 1);
        float w0 = __ldg(g_gs + e),     w1 = __ldg(g_gs + e + 1);
        float2 v0 = __ldg(&src[(size_t)t0 * 32 + lane]);
        float2 v1 = __ldg(&src[(size_t)t1 * 32 + lane]);
        acc.x += w0 * v0.x + w1 * v1.x;
        acc.y += w0 * v0.y + w1 * v1.y;
    }
    if (e < end) {
        int   t0 = __ldg(g_ts + e);
        float w0 = __ldg(g_gs + e);
        float2 v0 = __ldg(&src[(size_t)t0 * 32 + lane]);
        acc.x += w0 * v0.x;
        acc.y += w0 * v0.y;
    }

    size_t idx = (size_t)wg * 32 + lane;
    float2 old = src[idx];
    float2 nw  = make_float2(acc.x + old.x, acc.y + old.y);

    float2* accp = reinterpret_cast<float2*>(g_ACC);
    float2 a = accp[idx];
    a.x += nw.x; a.y += nw.y;
    accp[idx] = a;

    if (layer == 0) reinterpret_cast<float2*>(g_N)[idx] = nw;
}

// one warp per sample
__global__ void k_loss(const float* __restrict__ ue, const float* __restrict__ ie,
                       const int* __restrict__ users, const int* __restrict__ pos,
                       const int* __restrict__ neg, float* __restrict__ out) {
    int warp = (blockIdx.x * blockDim.x + threadIdx.x) >> 5;
    int lane = threadIdx.x & 31;
    if (warp >= BATCH) return;
    int u = users[warp], p = pos[warp], n = neg[warp];

    const float2* accp = reinterpret_cast<const float2*>(g_ACC);
    float2 uv = accp[(size_t)u * 32 + lane];
    float2 pv = accp[(size_t)(N_USERS + p) * 32 + lane];
    float2 nv = accp[(size_t)(N_USERS + n) * 32 + lane];
    float s = uv.x * (nv.x - pv.x) + uv.y * (nv.y - pv.y);   // neg - pos partial

    const float2* up = reinterpret_cast<const float2*>(ue + (size_t)u * EMB_DIM);
    const float2* pp = reinterpret_cast<const float2*>(ie + (size_t)p * EMB_DIM);
    const float2* np = reinterpret_cast<const float2*>(ie + (size_t)n * EMB_DIM);
    float2 a = up[lane], b = pp[lane], c = np[lane];
    float r = a.x*a.x + a.y*a.y + b.x*b.x + b.y*b.y + c.x*c.x + c.y*c.y;

    #pragma unroll
    for (int o = 16; o; o >>= 1) {
        s += __shfl_xor_sync(0xFFFFFFFFu, s, o);
        r += __shfl_xor_sync(0xFFFFFFFFu, r, o);
    }
    if (lane == 0) {
        float x  = s;
        float sp = (x > 0.0f) ? x + log1pf(expf(-x)) : log1pf(expf(x));
        atomicAdd(&out[0], sp * (1.0f / BATCH));
        atomicAdd(&out[1], r * EMB_REG);
    }
}

// ---------------- launch ----------------
extern "C" void kernel_launch(void* const* d_in, const int* in_sizes, int n_in,
                              void* d_out, int out_size) {
    const float* ue    = (const float*)d_in[0];
    const float* ie    = (const float*)d_in[1];
    const int*   all_h = (const int*)  d_in[2];
    const int*   all_t = (const int*)  d_in[3];
    const int*   users = (const int*)  d_in[4];
    const int*   pos   = (const int*)  d_in[5];
    const int*   neg   = (const int*)  d_in[6];
    float*       out   = (float*)d_out;

    const int T = 256;
    const int gNode = (N_NODES + T - 1) / T;
    const int gEdge = (N_EDGES + T - 1) / T;
    const int gVec  = (N_NODES * VEC + T - 1) / T;
    const int gCsr  = ((N_NODES * 32) + T - 1) / T;   // warp per row

    k_zero   <<<gNode, T>>>(out);
    k_deg    <<<gEdge, T>>>(all_h);
    k_scan1  <<<NBLK, SCAN_BLK>>>();
    k_scan2  <<<1, 1024>>>();
    k_scan3  <<<gNode, T>>>();
    k_scatter<<<gEdge, T>>>(all_h, all_t);
    k_init   <<<gVec,  T>>>(ue, ie);

    k_csr<<<gCsr, T>>>(0);
    k_csr<<<gCsr, T>>>(1);

    k_loss<<<(BATCH * 32 + T - 1) / T, T>>>(ue, ie, users, pos, neg, out);
}